// round 1
// baseline (speedup 1.0000x reference)
#include <cuda_runtime.h>
#include <math.h>

// CPn lattice action, B x 64x64 lattice, n=6 angles/site -> z in C^4.
// One pass: each block computes z for a 32-row tile + 1 halo row into SMEM,
// then accumulates |z(s) . z(s+mu)|^2 - 1 for both shifts locally.

#define LSZ 64
#define SITES (LSZ * LSZ)          // 4096
#define NCH 6
#define RPB 32                     // rows per block
#define TPB (LSZ / RPB)            // tiles per batch = 2
#define TILE_SITES (RPB * LSZ)     // 2048 owned sites
#define HALO_SITES ((RPB + 1) * LSZ) // 2112 (one extra row)
#define NTHREADS 256
#define MAXB 1024

__device__ float g_partial[MAXB * TPB];

__global__ void __launch_bounds__(NTHREADS, 3)
cpn_main(const float* __restrict__ phi)
{
    extern __shared__ float sm[];
    float* zr0 = sm + 0 * HALO_SITES;
    float* zr1 = sm + 1 * HALO_SITES;
    float* zr2 = sm + 2 * HALO_SITES;
    float* zr3 = sm + 3 * HALO_SITES;
    float* zi0 = sm + 4 * HALO_SITES;
    float* zi1 = sm + 5 * HALO_SITES;
    float* zi2 = sm + 6 * HALO_SITES;

    const int b    = blockIdx.x;
    const int tile = blockIdx.y;
    const int r0   = tile * RPB;
    const float* __restrict__ phib = phi + (size_t)b * SITES * NCH;

    const float PI_F   = 3.14159265358979323846f;
    const float TWOPI  = 6.28318530717958647692f;
    const float INVPI  = 0.318309886183790671538f;
    const float INV2PI = 0.159154943091895335769f;

    // Phase 1: compute z for tile + halo row (trig once per site)
    for (int i = threadIdx.x; i < HALO_SITES; i += NTHREADS) {
        int gr = r0 + (i >> 6);
        if (gr >= LSZ) gr -= LSZ;
        int sg = (gr << 6) | (i & 63);
        const float2* p = reinterpret_cast<const float2*>(phib + sg * NCH);
        float2 v0 = p[0];
        float2 v1 = p[1];
        float2 v2 = p[2];
        float a[6] = {v0.x, v0.y, v1.x, v1.y, v2.x, v2.y};
        float s[6], c[6];
        #pragma unroll
        for (int k = 0; k < 5; k++) {
            float m = a[k] - floorf(a[k] * INVPI) * PI_F;   // mod pi (floored)
            s[k] = __sinf(m);
            c[k] = __cosf(m);
        }
        {
            float m = a[5] - floorf(a[5] * INV2PI) * TWOPI; // mod 2pi
            s[5] = __sinf(m);
            c[5] = __cosf(m);
        }
        // x = [c0, c1*s0, c2*s0s1, ..., c5*s0..s4, s0..s5]
        float sc = s[0];
        float x1 = c[1] * sc; sc *= s[1];
        float x2 = c[2] * sc; sc *= s[2];
        float x3 = c[3] * sc; sc *= s[3];
        float x4 = c[4] * sc; sc *= s[4];
        float x5 = c[5] * sc; sc *= s[5];
        zr0[i] = c[0];
        zr1[i] = x1;
        zr2[i] = x2;
        zr3[i] = x3;
        zi0[i] = x4;   // zi = (x4, x5, x6, 0) -- 4th component is identically 0
        zi1[i] = x5;
        zi2[i] = sc;   // x6
    }
    __syncthreads();

    // Phase 2: accumulate |z(s) . z(s+mu)|^2 - 1 over owned sites, both shifts
    float acc = 0.0f;
    for (int i = threadIdx.x; i < TILE_SITES; i += NTHREADS) {
        float ur0 = zr0[i], ur1 = zr1[i], ur2 = zr2[i], ur3 = zr3[i];
        float ui0 = zi0[i], ui1 = zi1[i], ui2 = zi2[i];
        int j0 = i + LSZ;                         // +row neighbor (in halo)
        int j1 = (i & ~63) | ((i + 1) & 63);      // +col neighbor (wraps in-row)
        #pragma unroll
        for (int d = 0; d < 2; d++) {
            int j = (d == 0) ? j0 : j1;
            float a0 = zr0[j], a1 = zr1[j], a2 = zr2[j], a3 = zr3[j];
            float b0 = zi0[j], b1 = zi1[j], b2 = zi2[j];
            float dre = ur0*a0 + ur1*a1 + ur2*a2 + ur3*a3
                      - ui0*b0 - ui1*b1 - ui2*b2;
            float dim = ur0*b0 + ur1*b1 + ur2*b2
                      + ui0*a0 + ui1*a1 + ui2*a2;
            acc += dre*dre + dim*dim - 1.0f;
        }
    }

    // Block reduction
    #pragma unroll
    for (int o = 16; o > 0; o >>= 1)
        acc += __shfl_down_sync(0xffffffffu, acc, o);
    __shared__ float red[NTHREADS / 32];
    int wid = threadIdx.x >> 5;
    if ((threadIdx.x & 31) == 0) red[wid] = acc;
    __syncthreads();
    if (threadIdx.x < NTHREADS / 32) {
        float v = red[threadIdx.x];
        #pragma unroll
        for (int o = (NTHREADS / 64); o > 0; o >>= 1)
            v += __shfl_down_sync((1u << (NTHREADS / 32)) - 1u, v, o);
        if (threadIdx.x == 0)
            g_partial[b * TPB + tile] = v;
    }
}

__global__ void cpn_reduce(float* __restrict__ out, int B)
{
    int b = blockIdx.x * blockDim.x + threadIdx.x;
    if (b < B) {
        float s = 0.0f;
        #pragma unroll
        for (int t = 0; t < TPB; t++) s += g_partial[b * TPB + t];
        out[b] = -4.0f * s;   // -N * BETA, N = (n+1+1)/2 = 4, BETA = 1
    }
}

extern "C" void kernel_launch(void* const* d_in, const int* in_sizes, int n_in,
                              void* d_out, int out_size)
{
    const float* phi = (const float*)d_in[0];
    // d_in[1] (shift) is a fixed roll of the site index; computed analytically.
    int B = in_sizes[0] / (SITES * NCH);
    if (B > MAXB) B = MAXB;

    const size_t smem = (size_t)HALO_SITES * 7 * sizeof(float); // 59136 B
    cudaFuncSetAttribute(cpn_main, cudaFuncAttributeMaxDynamicSharedMemorySize, (int)smem);

    dim3 grid(B, TPB);
    cpn_main<<<grid, NTHREADS, smem>>>(phi);
    cpn_reduce<<<(B + 255) / 256, 256>>>((float*)d_out, B);
}

// round 3
// speedup vs baseline: 1.0043x; 1.0043x over previous
#include <cuda_runtime.h>
#include <math.h>

// CPn lattice action, B x 64x64 lattice, n=6 angles/site -> z in C^4.
// Phase 1: compute z (trig) for a 32-row tile + 1 halo row into SMEM (SoA).
// Phase 2: site-PAIR vectorized accumulation with packed f32x2 FMA; smem
// pairs are 8B-aligned so LDS.64 delivers packed operands for free.

#define LSZ 64
#define SITES (LSZ * LSZ)            // 4096
#define NCH 6
#define RPB 32                       // rows per block
#define TPB (LSZ / RPB)              // tiles per batch = 2
#define TILE_SITES (RPB * LSZ)       // 2048 owned sites
#define HALO_SITES ((RPB + 1) * LSZ) // 2112
#define NTHREADS 256
#define MAXB 1024

typedef unsigned long long u64;

__device__ __forceinline__ u64 pk2(float x, float y) {
    u64 r; asm("mov.b64 %0, {%1,%2};" : "=l"(r) : "f"(x), "f"(y)); return r;
}
__device__ __forceinline__ void upk2(u64 v, float& x, float& y) {
    asm("mov.b64 {%0,%1}, %2;" : "=f"(x), "=f"(y) : "l"(v));
}
__device__ __forceinline__ u64 fma2(u64 a, u64 b, u64 c) {
    u64 d; asm("fma.rn.f32x2 %0, %1, %2, %3;" : "=l"(d) : "l"(a), "l"(b), "l"(c)); return d;
}
__device__ __forceinline__ u64 mul2(u64 a, u64 b) {
    u64 d; asm("mul.rn.f32x2 %0, %1, %2;" : "=l"(d) : "l"(a), "l"(b)); return d;
}
__device__ __forceinline__ u64 sub2(u64 a, u64 b) {
    u64 d; asm("sub.rn.f32x2 %0, %1, %2;" : "=l"(d) : "l"(a), "l"(b)); return d;
}

__global__ void __launch_bounds__(NTHREADS, 3)
cpn_main(const float* __restrict__ phi, float* __restrict__ out)
{
    extern __shared__ float sm[];
    // 7 SoA planes: zr0..zr3, zi0..zi2
    const int b    = blockIdx.x;
    const int tile = blockIdx.y;
    const int r0   = tile * RPB;
    const float* __restrict__ phib = phi + (size_t)b * SITES * NCH;

    const float PI_F   = 3.14159265358979323846f;
    const float TWOPI  = 6.28318530717958647692f;
    const float INVPI  = 0.318309886183790671538f;
    const float INV2PI = 0.159154943091895335769f;

    // ---- Phase 1: z for tile + halo row (trig once per site) ----
    for (int i = threadIdx.x; i < HALO_SITES; i += NTHREADS) {
        int gr = r0 + (i >> 6);
        if (gr >= LSZ) gr -= LSZ;
        int sg = (gr << 6) | (i & 63);
        const float2* p = reinterpret_cast<const float2*>(phib + sg * NCH);
        float2 v0 = p[0];
        float2 v1 = p[1];
        float2 v2 = p[2];
        float a[6] = {v0.x, v0.y, v1.x, v1.y, v2.x, v2.y};
        float s[6], c[6];
        #pragma unroll
        for (int k = 0; k < 5; k++) {
            float m = a[k] - floorf(a[k] * INVPI) * PI_F;   // mod pi
            s[k] = __sinf(m);
            c[k] = __cosf(m);
        }
        {
            float m = a[5] - floorf(a[5] * INV2PI) * TWOPI; // mod 2pi
            s[5] = __sinf(m);
            c[5] = __cosf(m);
        }
        float sc = s[0];
        float x1 = c[1] * sc; sc *= s[1];
        float x2 = c[2] * sc; sc *= s[2];
        float x3 = c[3] * sc; sc *= s[3];
        float x4 = c[4] * sc; sc *= s[4];
        float x5 = c[5] * sc; sc *= s[5];
        sm[0 * HALO_SITES + i] = c[0];
        sm[1 * HALO_SITES + i] = x1;
        sm[2 * HALO_SITES + i] = x2;
        sm[3 * HALO_SITES + i] = x3;
        sm[4 * HALO_SITES + i] = x4;  // zi0
        sm[5 * HALO_SITES + i] = x5;  // zi1
        sm[6 * HALO_SITES + i] = sc;  // zi2  (zi3 == 0 identically)
    }
    __syncthreads();

    // ---- Phase 2: site-pair packed accumulation ----
    // acc2 accumulates dre^2 + dim^2 over both shifts; the "-1" terms are a
    // constant (2 per site) folded in at the end.
    u64 acc2 = pk2(0.0f, 0.0f);
    for (int p = threadIdx.x; p < TILE_SITES / 2; p += NTHREADS) {
        int i = 2 * p;                       // even site index: 8B aligned pair
        int rowbase = i & ~63;
        int inext = rowbase | ((i + 2) & 63); // next aligned pair in-row (wraps)

        u64 S[7], R[7], C[7];
        #pragma unroll
        for (int k = 0; k < 7; k++) {
            const float* pl = sm + k * HALO_SITES;
            S[k] = *reinterpret_cast<const u64*>(pl + i);        // self pair
            R[k] = *reinterpret_cast<const u64*>(pl + i + LSZ);  // +row pair
            u64 Pn = *reinterpret_cast<const u64*>(pl + inext);  // next pair
            // +col neighbor pair = (self.hi, next.lo)
            float slo, shi, plo, phi_;
            upk2(S[k], slo, shi);
            upk2(Pn, plo, phi_);
            C[k] = pk2(shi, plo);
        }

        #pragma unroll
        for (int d = 0; d < 2; d++) {
            u64* N = (d == 0) ? R : C;
            // dre = S0*N0+S1*N1+S2*N2+S3*N3 - (S4*N4+S5*N5+S6*N6)
            u64 pos = mul2(S[0], N[0]);
            pos = fma2(S[1], N[1], pos);
            pos = fma2(S[2], N[2], pos);
            pos = fma2(S[3], N[3], pos);
            u64 neg = mul2(S[4], N[4]);
            neg = fma2(S[5], N[5], neg);
            neg = fma2(S[6], N[6], neg);
            u64 dre = sub2(pos, neg);
            // dim = S0*N4+S1*N5+S2*N6 + S4*N0+S5*N1+S6*N2
            u64 dim = mul2(S[0], N[4]);
            dim = fma2(S[1], N[5], dim);
            dim = fma2(S[2], N[6], dim);
            dim = fma2(S[4], N[0], dim);
            dim = fma2(S[5], N[1], dim);
            dim = fma2(S[6], N[2], dim);
            acc2 = fma2(dre, dre, acc2);
            acc2 = fma2(dim, dim, acc2);
        }
    }
    float alo, ahi;
    upk2(acc2, alo, ahi);
    float acc = alo + ahi;

    // Block reduction
    #pragma unroll
    for (int o = 16; o > 0; o >>= 1)
        acc += __shfl_down_sync(0xffffffffu, acc, o);
    __shared__ float red[NTHREADS / 32];
    int wid = threadIdx.x >> 5;
    if ((threadIdx.x & 31) == 0) red[wid] = acc;
    __syncthreads();
    if (threadIdx.x == 0) {
        float v = 0.0f;
        #pragma unroll
        for (int w = 0; w < NTHREADS / 32; w++) v += red[w];
        // action contribution: -4 * sum(dre^2 + dim^2 - 1)
        v = -4.0f * (v - 2.0f * (float)TILE_SITES);
        atomicAdd(out + b, v);
    }
}

extern "C" void kernel_launch(void* const* d_in, const int* in_sizes, int n_in,
                              void* d_out, int out_size)
{
    const float* phi = (const float*)d_in[0];
    // d_in[1] (shift) is a fixed (+1 row, +1 col) roll; handled analytically.
    int B = in_sizes[0] / (SITES * NCH);
    if (B > MAXB) B = MAXB;

    cudaMemsetAsync(d_out, 0, (size_t)out_size * sizeof(float), 0);

    const size_t smem = (size_t)HALO_SITES * 7 * sizeof(float); // 59136 B
    cudaFuncSetAttribute(cpn_main, cudaFuncAttributeMaxDynamicSharedMemorySize, (int)smem);

    dim3 grid(B, TPB);
    cpn_main<<<grid, NTHREADS, smem>>>(phi, (float*)d_out);
}

// round 4
// speedup vs baseline: 1.5624x; 1.5558x over previous
#include <cuda_runtime.h>
#include <math.h>

// CPn lattice action, B x 64x64 lattice, n=6 angles/site -> z in C^4.
// Fully register-resident: one block per batch (128 thr), each warp owns 16
// rows; lane l owns columns (2l, 2l+1) packed as f32x2. Row-neighbor via
// sequential row iteration (S<-R rotation), col-neighbor via 1 SHFL/component.
// No z smem, no hot-loop syncthreads.

#define LSZ 64
#define SITES (LSZ * LSZ)      // 4096
#define NCH 6
#define RPW 16                 // rows per warp
#define NWARPS 4
#define NTHREADS (NWARPS * 32)

typedef unsigned long long u64;

__device__ __forceinline__ u64 pk2(float x, float y) {
    u64 r; asm("mov.b64 %0, {%1,%2};" : "=l"(r) : "f"(x), "f"(y)); return r;
}
__device__ __forceinline__ void upk2(u64 v, float& x, float& y) {
    asm("mov.b64 {%0,%1}, %2;" : "=f"(x), "=f"(y) : "l"(v));
}
__device__ __forceinline__ u64 fma2(u64 a, u64 b, u64 c) {
    u64 d; asm("fma.rn.f32x2 %0, %1, %2, %3;" : "=l"(d) : "l"(a), "l"(b), "l"(c)); return d;
}
__device__ __forceinline__ u64 mul2(u64 a, u64 b) {
    u64 d; asm("mul.rn.f32x2 %0, %1, %2;" : "=l"(d) : "l"(a), "l"(b)); return d;
}
__device__ __forceinline__ u64 sub2(u64 a, u64 b) {
    u64 d; asm("sub.rn.f32x2 %0, %1, %2;" : "=l"(d) : "l"(a), "l"(b)); return d;
}

// z-vector (7 comps) from 6 angles: x = [c0, c1*s0, c2*s0s1, ..., c5*s0..s4, s0..s5]
__device__ __forceinline__ void site_z(const float a[6], float z[7]) {
    const float PI_F   = 3.14159265358979323846f;
    const float TWOPI  = 6.28318530717958647692f;
    const float INVPI  = 0.318309886183790671538f;
    const float INV2PI = 0.159154943091895335769f;
    float s[6], c[6];
    #pragma unroll
    for (int k = 0; k < 5; k++) {
        float m = a[k] - floorf(a[k] * INVPI) * PI_F;   // mod pi (floored)
        s[k] = __sinf(m);
        c[k] = __cosf(m);
    }
    {
        float m = a[5] - floorf(a[5] * INV2PI) * TWOPI; // mod 2pi
        s[5] = __sinf(m);
        c[5] = __cosf(m);
    }
    float sc = s[0];
    z[0] = c[0];
    z[1] = c[1] * sc; sc *= s[1];
    z[2] = c[2] * sc; sc *= s[2];
    z[3] = c[3] * sc; sc *= s[3];
    z[4] = c[4] * sc; sc *= s[4];   // zi0
    z[5] = c[5] * sc; sc *= s[5];   // zi1
    z[6] = sc;                      // zi2 (zi3 == 0 identically)
}

// acc += dre^2 + dim^2 for z(S) . conj-structured z(N), packed over 2 sites
__device__ __forceinline__ void accdot(const u64 S[7], const u64 N[7], u64& acc) {
    u64 pos = mul2(S[0], N[0]);
    pos = fma2(S[1], N[1], pos);
    pos = fma2(S[2], N[2], pos);
    pos = fma2(S[3], N[3], pos);
    u64 neg = mul2(S[4], N[4]);
    neg = fma2(S[5], N[5], neg);
    neg = fma2(S[6], N[6], neg);
    u64 dre = sub2(pos, neg);
    u64 dim = mul2(S[0], N[4]);
    dim = fma2(S[1], N[5], dim);
    dim = fma2(S[2], N[6], dim);
    dim = fma2(S[4], N[0], dim);
    dim = fma2(S[5], N[1], dim);
    dim = fma2(S[6], N[2], dim);
    acc = fma2(dre, dre, acc);
    acc = fma2(dim, dim, acc);
}

__global__ void __launch_bounds__(NTHREADS, 8)
cpn_main(const float* __restrict__ phi, float* __restrict__ out)
{
    const int b    = blockIdx.x;
    const int w    = threadIdx.x >> 5;
    const int lane = threadIdx.x & 31;
    const int r0   = w * RPW;
    const float4* __restrict__ f4 =
        reinterpret_cast<const float4*>(phi + (size_t)b * SITES * NCH);
    // lane l handles sites (row, 2l) and (row, 2l+1): 12 floats = 3 float4,
    // f4 index = row*96 + 3*lane (row has 64*6/4 = 96 float4s)
    const int lidx = 3 * lane;

    // z of first owned row
    u64 S[7];
    {
        int base = r0 * 96 + lidx;
        float4 v0 = f4[base], v1 = f4[base + 1], v2 = f4[base + 2];
        float aA[6] = {v0.x, v0.y, v0.z, v0.w, v1.x, v1.y};
        float aB[6] = {v1.z, v1.w, v2.x, v2.y, v2.z, v2.w};
        float zA[7], zB[7];
        site_z(aA, zA);
        site_z(aB, zB);
        #pragma unroll
        for (int k = 0; k < 7; k++) S[k] = pk2(zA[k], zB[k]);
    }

    u64 acc2 = pk2(0.0f, 0.0f);
    #pragma unroll 2
    for (int r = 1; r <= RPW; r++) {
        int gr = r0 + r;
        if (gr >= LSZ) gr -= LSZ;
        // issue next-row loads early
        int base = gr * 96 + lidx;
        float4 v0 = f4[base], v1 = f4[base + 1], v2 = f4[base + 2];

        // column-direction dot for current row (independent of the loads):
        // neighbor of (2l, 2l+1) is (2l+1, 2l+2) = (S.hi, shfl_next(S.lo))
        {
            u64 C[7];
            #pragma unroll
            for (int k = 0; k < 7; k++) {
                float slo, shi;
                upk2(S[k], slo, shi);
                float nlo = __shfl_sync(0xffffffffu, slo, (lane + 1) & 31);
                C[k] = pk2(shi, nlo);
            }
            accdot(S, C, acc2);
        }

        // z of next row
        u64 R[7];
        {
            float aA[6] = {v0.x, v0.y, v0.z, v0.w, v1.x, v1.y};
            float aB[6] = {v1.z, v1.w, v2.x, v2.y, v2.z, v2.w};
            float zA[7], zB[7];
            site_z(aA, zA);
            site_z(aB, zB);
            #pragma unroll
            for (int k = 0; k < 7; k++) R[k] = pk2(zA[k], zB[k]);
        }

        // row-direction dot, then rotate
        accdot(S, R, acc2);
        #pragma unroll
        for (int k = 0; k < 7; k++) S[k] = R[k];
    }

    // Reduce: packed -> scalar -> warp -> block
    float alo, ahi;
    upk2(acc2, alo, ahi);
    float acc = alo + ahi;
    #pragma unroll
    for (int o = 16; o > 0; o >>= 1)
        acc += __shfl_down_sync(0xffffffffu, acc, o);

    __shared__ float red[NWARPS];
    if (lane == 0) red[w] = acc;
    __syncthreads();
    if (threadIdx.x == 0) {
        float v = red[0] + red[1] + red[2] + red[3];
        // action = -4 * sum(dre^2 + dim^2 - 1); 2 directions * 4096 sites
        out[b] = -4.0f * (v - 2.0f * (float)SITES);
    }
}

extern "C" void kernel_launch(void* const* d_in, const int* in_sizes, int n_in,
                              void* d_out, int out_size)
{
    const float* phi = (const float*)d_in[0];
    // d_in[1] (shift) is the fixed (+1 row, +1 col) roll; handled analytically.
    int B = in_sizes[0] / (SITES * NCH);
    cpn_main<<<B, NTHREADS>>>(phi, (float*)d_out);
}

// round 5
// speedup vs baseline: 1.8105x; 1.1588x over previous
#include <cuda_runtime.h>
#include <math.h>

// CPn lattice action, B x 64x64 lattice, n=6 angles/site -> z in C^4.
// 2 CTAs per batch (32 rows each), 4 warps x 8 rows, lane owns a column pair
// packed as f32x2. Trig once per site using the identities
//   sin(mod(a,pi)) = |sin a|,  cos(mod(a,pi)) = cos(a)*sign(sin a),
//   sin/cos(mod(a,2pi)) = sin/cos(a)       (no explicit range reduction).
// Warps exchange their first-row z through smem so only the CTA-boundary
// row (1/32) needs halo recompute. Col-neighbor via 1 SHFL per component.

#define LSZ 64
#define SITES (LSZ * LSZ)      // 4096
#define NCH 6
#define RPW 8                  // rows per warp
#define NWARPS 4               // rows per CTA = 32
#define TPB 2                  // CTAs (tiles) per batch
#define NTHREADS (NWARPS * 32)

typedef unsigned long long u64;

__device__ __forceinline__ u64 pk2(float x, float y) {
    u64 r; asm("mov.b64 %0, {%1,%2};" : "=l"(r) : "f"(x), "f"(y)); return r;
}
__device__ __forceinline__ void upk2(u64 v, float& x, float& y) {
    asm("mov.b64 {%0,%1}, %2;" : "=f"(x), "=f"(y) : "l"(v));
}
__device__ __forceinline__ u64 fma2(u64 a, u64 b, u64 c) {
    u64 d; asm("fma.rn.f32x2 %0, %1, %2, %3;" : "=l"(d) : "l"(a), "l"(b), "l"(c)); return d;
}
__device__ __forceinline__ u64 mul2(u64 a, u64 b) {
    u64 d; asm("mul.rn.f32x2 %0, %1, %2;" : "=l"(d) : "l"(a), "l"(b)); return d;
}
__device__ __forceinline__ u64 sub2(u64 a, u64 b) {
    u64 d; asm("sub.rn.f32x2 %0, %1, %2;" : "=l"(d) : "l"(a), "l"(b)); return d;
}

// z-vector (7 comps) from 6 angles, no explicit mod:
// x = [c0, c1*s0, c2*s0s1, ..., c5*s0..s4, s0..s5]
__device__ __forceinline__ void site_z(const float a[6], float z[7]) {
    float s[6], c[6];
    #pragma unroll
    for (int k = 0; k < 5; k++) {
        float sa = __sinf(a[k]);
        float ca = __cosf(a[k]);
        s[k] = fabsf(sa);                      // sin(mod(a,pi))
        c[k] = __uint_as_float(__float_as_uint(ca) ^
                               (__float_as_uint(sa) & 0x80000000u)); // cos*sign(sin)
    }
    s[5] = __sinf(a[5]);                       // mod 2pi is a no-op for sin/cos
    c[5] = __cosf(a[5]);
    float sc = s[0];
    z[0] = c[0];
    z[1] = c[1] * sc; sc *= s[1];
    z[2] = c[2] * sc; sc *= s[2];
    z[3] = c[3] * sc; sc *= s[3];
    z[4] = c[4] * sc; sc *= s[4];   // zi0
    z[5] = c[5] * sc; sc *= s[5];   // zi1
    z[6] = sc;                      // zi2 (zi3 == 0 identically)
}

__device__ __forceinline__ void load_row_z(const float4* __restrict__ f4,
                                           int row, int lidx, u64 Z[7]) {
    int base = row * 96 + lidx;                // 96 float4 per row
    float4 v0 = f4[base], v1 = f4[base + 1], v2 = f4[base + 2];
    float aA[6] = {v0.x, v0.y, v0.z, v0.w, v1.x, v1.y};
    float aB[6] = {v1.z, v1.w, v2.x, v2.y, v2.z, v2.w};
    float zA[7], zB[7];
    site_z(aA, zA);
    site_z(aB, zB);
    #pragma unroll
    for (int k = 0; k < 7; k++) Z[k] = pk2(zA[k], zB[k]);
}

// acc += dre^2 + dim^2, packed over 2 sites
__device__ __forceinline__ void accdot(const u64 S[7], const u64 N[7], u64& acc) {
    u64 pos = mul2(S[0], N[0]);
    pos = fma2(S[1], N[1], pos);
    pos = fma2(S[2], N[2], pos);
    pos = fma2(S[3], N[3], pos);
    u64 neg = mul2(S[4], N[4]);
    neg = fma2(S[5], N[5], neg);
    neg = fma2(S[6], N[6], neg);
    u64 dre = sub2(pos, neg);
    u64 dim = mul2(S[0], N[4]);
    dim = fma2(S[1], N[5], dim);
    dim = fma2(S[2], N[6], dim);
    dim = fma2(S[4], N[0], dim);
    dim = fma2(S[5], N[1], dim);
    dim = fma2(S[6], N[2], dim);
    acc = fma2(dre, dre, acc);
    acc = fma2(dim, dim, acc);
}

// column-direction dot: neighbor of pair (2l, 2l+1) is (2l+1, 2l+2)
__device__ __forceinline__ void coldot(const u64 S[7], int lane, u64& acc) {
    u64 C[7];
    #pragma unroll
    for (int k = 0; k < 7; k++) {
        float slo, shi;
        upk2(S[k], slo, shi);
        float nlo = __shfl_sync(0xffffffffu, slo, (lane + 1) & 31);
        C[k] = pk2(shi, nlo);
    }
    accdot(S, C, acc);
}

__global__ void __launch_bounds__(NTHREADS, 8)
cpn_main(const float* __restrict__ phi, float* __restrict__ out)
{
    const int b    = blockIdx.x;
    const int tile = blockIdx.y;
    const int w    = threadIdx.x >> 5;
    const int lane = threadIdx.x & 31;
    const int r0   = tile * (NWARPS * RPW) + w * RPW;   // first owned row
    const float4* __restrict__ f4 =
        reinterpret_cast<const float4*>(phi + (size_t)b * SITES * NCH);
    const int lidx = 3 * lane;

    __shared__ u64 firstz[NWARPS][7][32];
    __shared__ float red[NWARPS];

    // first owned row -> S, publish to smem for the warp below
    u64 S[7];
    load_row_z(f4, r0, lidx, S);
    #pragma unroll
    for (int k = 0; k < 7; k++) firstz[w][k][lane] = S[k];
    __syncthreads();

    u64 acc2 = pk2(0.0f, 0.0f);
    #pragma unroll 2
    for (int r = 1; r < RPW; r++) {
        u64 R[7];
        load_row_z(f4, r0 + r, lidx, R);   // loads issue before coldot math
        coldot(S, lane, acc2);
        accdot(S, R, acc2);                // row-direction
        #pragma unroll
        for (int k = 0; k < 7; k++) S[k] = R[k];
    }

    // last owned row: col dot + row dot vs next warp's first row (or halo)
    coldot(S, lane, acc2);
    u64 N[7];
    if (w < NWARPS - 1) {
        #pragma unroll
        for (int k = 0; k < 7; k++) N[k] = firstz[w + 1][k][lane];
    } else {
        int gr = r0 + RPW;                 // CTA-boundary row
        if (gr >= LSZ) gr -= LSZ;
        load_row_z(f4, gr, lidx, N);
    }
    accdot(S, N, acc2);

    // reduce: packed -> scalar -> warp -> block -> atomic
    float alo, ahi;
    upk2(acc2, alo, ahi);
    float acc = alo + ahi;
    #pragma unroll
    for (int o = 16; o > 0; o >>= 1)
        acc += __shfl_down_sync(0xffffffffu, acc, o);
    if (lane == 0) red[w] = acc;
    __syncthreads();
    if (threadIdx.x == 0) {
        float v = red[0] + red[1] + red[2] + red[3];
        // per-CTA contribution: -4 * (sum - 1 per (site,dir)); 2*32*64 terms
        v = -4.0f * (v - 2.0f * (float)(NWARPS * RPW * LSZ));
        atomicAdd(out + b, v);
    }
}

extern "C" void kernel_launch(void* const* d_in, const int* in_sizes, int n_in,
                              void* d_out, int out_size)
{
    const float* phi = (const float*)d_in[0];
    // d_in[1] (shift) is the fixed (+1 row, +1 col) roll; handled analytically.
    int B = in_sizes[0] / (SITES * NCH);
    cudaMemsetAsync(d_out, 0, (size_t)out_size * sizeof(float), 0);
    dim3 grid(B, TPB);
    cpn_main<<<grid, NTHREADS>>>(phi, (float*)d_out);
}

// round 6
// speedup vs baseline: 2.1360x; 1.1798x over previous
#include <cuda_runtime.h>
#include <math.h>

// CPn lattice action, B x 64x64 lattice, n=6 angles/site -> z in C^4.
// ONE 256-thread CTA per batch: 8 warps x 8 rows, lane owns a column pair
// packed as f32x2. Row-neighbor via sequential row iteration with
// software-pipelined (prefetched) loads; warp-boundary rows exchanged via
// smem (incl. the 63->0 wrap, so zero halo recompute). Col-neighbor via
// 1 SHFL per component. Direct out[b] store: no memset, no atomics.
// Trig identities: sin(mod(a,pi)) = |sin a|, cos(mod(a,pi)) = cos(a)*sign(sin a),
// mod 2pi is a no-op under sin/cos.

#define LSZ 64
#define SITES (LSZ * LSZ)      // 4096
#define NCH 6
#define RPW 8                  // rows per warp
#define NWARPS 8               // 8 warps -> 64 rows = whole batch
#define NTHREADS (NWARPS * 32) // 256

typedef unsigned long long u64;

__device__ __forceinline__ u64 pk2(float x, float y) {
    u64 r; asm("mov.b64 %0, {%1,%2};" : "=l"(r) : "f"(x), "f"(y)); return r;
}
__device__ __forceinline__ void upk2(u64 v, float& x, float& y) {
    asm("mov.b64 {%0,%1}, %2;" : "=f"(x), "=f"(y) : "l"(v));
}
__device__ __forceinline__ u64 fma2(u64 a, u64 b, u64 c) {
    u64 d; asm("fma.rn.f32x2 %0, %1, %2, %3;" : "=l"(d) : "l"(a), "l"(b), "l"(c)); return d;
}
__device__ __forceinline__ u64 mul2(u64 a, u64 b) {
    u64 d; asm("mul.rn.f32x2 %0, %1, %2;" : "=l"(d) : "l"(a), "l"(b)); return d;
}
__device__ __forceinline__ u64 sub2(u64 a, u64 b) {
    u64 d; asm("sub.rn.f32x2 %0, %1, %2;" : "=l"(d) : "l"(a), "l"(b)); return d;
}

// z-vector (7 comps) from 6 angles, no explicit range reduction
__device__ __forceinline__ void site_z(const float a[6], float z[7]) {
    float s[6], c[6];
    #pragma unroll
    for (int k = 0; k < 5; k++) {
        float sa = __sinf(a[k]);
        float ca = __cosf(a[k]);
        s[k] = fabsf(sa);
        c[k] = __uint_as_float(__float_as_uint(ca) ^
                               (__float_as_uint(sa) & 0x80000000u));
    }
    s[5] = __sinf(a[5]);
    c[5] = __cosf(a[5]);
    float sc = s[0];
    z[0] = c[0];
    z[1] = c[1] * sc; sc *= s[1];
    z[2] = c[2] * sc; sc *= s[2];
    z[3] = c[3] * sc; sc *= s[3];
    z[4] = c[4] * sc; sc *= s[4];   // zi0
    z[5] = c[5] * sc; sc *= s[5];   // zi1
    z[6] = sc;                      // zi2 (zi3 == 0 identically)
}

__device__ __forceinline__ void raw_to_z(float4 v0, float4 v1, float4 v2, u64 Z[7]) {
    float aA[6] = {v0.x, v0.y, v0.z, v0.w, v1.x, v1.y};
    float aB[6] = {v1.z, v1.w, v2.x, v2.y, v2.z, v2.w};
    float zA[7], zB[7];
    site_z(aA, zA);
    site_z(aB, zB);
    #pragma unroll
    for (int k = 0; k < 7; k++) Z[k] = pk2(zA[k], zB[k]);
}

// acc += dre^2 + dim^2, packed over 2 sites
__device__ __forceinline__ void accdot(const u64 S[7], const u64 N[7], u64& acc) {
    u64 pos = mul2(S[0], N[0]);
    pos = fma2(S[1], N[1], pos);
    pos = fma2(S[2], N[2], pos);
    pos = fma2(S[3], N[3], pos);
    u64 neg = mul2(S[4], N[4]);
    neg = fma2(S[5], N[5], neg);
    neg = fma2(S[6], N[6], neg);
    u64 dre = sub2(pos, neg);
    u64 dim = mul2(S[0], N[4]);
    dim = fma2(S[1], N[5], dim);
    dim = fma2(S[2], N[6], dim);
    dim = fma2(S[4], N[0], dim);
    dim = fma2(S[5], N[1], dim);
    dim = fma2(S[6], N[2], dim);
    acc = fma2(dre, dre, acc);
    acc = fma2(dim, dim, acc);
}

// column-direction dot: neighbor of pair (2l, 2l+1) is (2l+1, 2l+2)
__device__ __forceinline__ void coldot(const u64 S[7], int lane, u64& acc) {
    u64 C[7];
    #pragma unroll
    for (int k = 0; k < 7; k++) {
        float slo, shi;
        upk2(S[k], slo, shi);
        float nlo = __shfl_sync(0xffffffffu, slo, (lane + 1) & 31);
        C[k] = pk2(shi, nlo);
    }
    accdot(S, C, acc);
}

__global__ void __launch_bounds__(NTHREADS, 4)
cpn_main(const float* __restrict__ phi, float* __restrict__ out)
{
    const int b    = blockIdx.x;
    const int w    = threadIdx.x >> 5;
    const int lane = threadIdx.x & 31;
    const int r0   = w * RPW;                 // first owned row
    const float4* __restrict__ f4 =
        reinterpret_cast<const float4*>(phi + (size_t)b * SITES * NCH);
    const int lidx = 3 * lane;                // 96 float4 per row

    __shared__ u64 firstz[NWARPS][7][32];
    __shared__ float red[NWARPS];

    // first owned row -> S, publish for the warp above (row wrap included)
    u64 S[7];
    {
        int base = r0 * 96 + lidx;
        raw_to_z(f4[base], f4[base + 1], f4[base + 2], S);
    }
    #pragma unroll
    for (int k = 0; k < 7; k++) firstz[w][k][lane] = S[k];
    __syncthreads();

    // prefetch raw row r0+1
    float4 w0, w1, w2;
    {
        int base = (r0 + 1) * 96 + lidx;
        w0 = f4[base]; w1 = f4[base + 1]; w2 = f4[base + 2];
    }

    u64 acc2 = pk2(0.0f, 0.0f);
    #pragma unroll 2
    for (int r = 1; r <= RPW - 2; r++) {
        // prefetch raw row r0+r+1 (in flight under this iteration's math)
        int base = (r0 + r + 1) * 96 + lidx;
        float4 n0 = f4[base], n1 = f4[base + 1], n2 = f4[base + 2];

        u64 R[7];
        raw_to_z(w0, w1, w2, R);
        coldot(S, lane, acc2);
        accdot(S, R, acc2);                // row-direction
        #pragma unroll
        for (int k = 0; k < 7; k++) S[k] = R[k];
        w0 = n0; w1 = n1; w2 = n2;
    }

    // last owned row (r = RPW-1), no further prefetch
    {
        u64 R[7];
        raw_to_z(w0, w1, w2, R);
        coldot(S, lane, acc2);
        accdot(S, R, acc2);
        #pragma unroll
        for (int k = 0; k < 7; k++) S[k] = R[k];
    }

    // boundary: col dot + row dot vs next warp's first row (wraps 63->0)
    coldot(S, lane, acc2);
    {
        u64 N[7];
        int nw = (w + 1) & (NWARPS - 1);
        #pragma unroll
        for (int k = 0; k < 7; k++) N[k] = firstz[nw][k][lane];
        accdot(S, N, acc2);
    }

    // reduce: packed -> scalar -> warp -> block
    float alo, ahi;
    upk2(acc2, alo, ahi);
    float acc = alo + ahi;
    #pragma unroll
    for (int o = 16; o > 0; o >>= 1)
        acc += __shfl_down_sync(0xffffffffu, acc, o);
    if (lane == 0) red[w] = acc;
    __syncthreads();
    if (threadIdx.x == 0) {
        float v = 0.0f;
        #pragma unroll
        for (int i = 0; i < NWARPS; i++) v += red[i];
        // action = -4 * sum(dre^2 + dim^2 - 1), 2 dirs * 4096 sites
        out[b] = -4.0f * (v - 2.0f * (float)SITES);
    }
}

extern "C" void kernel_launch(void* const* d_in, const int* in_sizes, int n_in,
                              void* d_out, int out_size)
{
    const float* phi = (const float*)d_in[0];
    // d_in[1] (shift) is the fixed (+1 row, +1 col) roll; handled analytically.
    int B = in_sizes[0] / (SITES * NCH);
    cpn_main<<<B, NTHREADS>>>(phi, (float*)d_out);
}